// round 17
// baseline (speedup 1.0000x reference)
#include <cuda_runtime.h>

#define NPTS    4096
#define BATCH   4
#define TPB     256
#define TILE    256                    // square tile side
#define T       (NPTS / TILE)          // 16
#define NSYM    (T * (T + 1) / 2)      // 136
#define NCROSS  (T * T)                // 256
#define PAIRS   (2 * NSYM + NCROSS)    // 528 blocks per batch
#define NBLOCKS (PAIRS * BATCH)        // 2112
#define ISUB    2                      // i sub-tiles per warp
#define JSTEPS  (TILE / 8)             // 32

// sqrt(2*log2(e)): p = x*SCALE  =>  p_i.p_j = 2*log2(e)*x_i.x_j
#define COORD_SCALE2 1.6986436f
#define BF_ONE 0x3F80u                 // bf16 1.0

__device__ float g_partials[NBLOCKS];
__device__ unsigned int g_count = 0;

typedef unsigned long long ull;

__device__ __forceinline__ float ex2f(float x) {
    float r;
    asm("ex2.approx.ftz.f32 %0, %1;" : "=f"(r) : "f"(x));
    return r;
}
__device__ __forceinline__ unsigned bfb(float x) {     // bf16 bits (round-nearest)
    unsigned short h;
    asm("cvt.rn.bf16.f32 %0, %1;" : "=h"(h) : "f"(x));
    return (unsigned)h;
}
__device__ __forceinline__ float bf2f(unsigned h) {    // exact bf16 -> f32
    return __uint_as_float(h << 16);
}
#define PK(lo, hi) ((lo) | ((hi) << 16))

__device__ __forceinline__ ull pack2(float lo, float hi) {
    ull r;
    asm("mov.b64 %0, {%1, %2};" : "=l"(r) : "f"(lo), "f"(hi));
    return r;
}
__device__ __forceinline__ void unpack2(ull v, float& lo, float& hi) {
    asm("mov.b64 {%0, %1}, %2;" : "=f"(lo), "=f"(hi) : "l"(v));
}
__device__ __forceinline__ ull fma2(ull a, ull b, ull c) {
    ull d;
    asm("fma.rn.f32x2 %0, %1, %2, %3;" : "=l"(d) : "l"(a), "l"(b), "l"(c));
    return d;
}
__device__ __forceinline__ ull mul2(ull a, ull b) {
    ull d;
    asm("mul.rn.f32x2 %0, %1, %2;" : "=l"(d) : "l"(a), "l"(b));
    return d;
}
// pack two f32 -> f16x2 (first asm source -> upper half; mirrors validated bf16x2 use)
__device__ __forceinline__ unsigned pack_f16x2(float lo, float hi) {
    unsigned r;
    asm("cvt.rn.f16x2.f32 %0, %1, %2;" : "=r"(r) : "f"(hi), "f"(lo));
    return r;
}
// packed exponential: 2 x 2^x in one MUFU op, f16 precision (10-bit mantissa)
__device__ __forceinline__ unsigned ex2_f16x2(unsigned x) {
    unsigned r;
    asm("ex2.approx.f16x2 %0, %1;" : "=r"(r) : "r"(x));
    return r;
}
// unpack f16x2 -> two f32 (exact widening)
__device__ __forceinline__ void unpack_f16x2(unsigned v, float& lo, float& hi) {
    unsigned short hlo, hhi;
    asm("mov.b32 {%0, %1}, %2;" : "=h"(hlo), "=h"(hhi) : "r"(v));
    asm("cvt.f32.f16 %0, %1;" : "=f"(lo) : "h"(hlo));
    asm("cvt.f32.f16 %0, %1;" : "=f"(hi) : "h"(hhi));
}

// D = A(16x16 bf16, row-major) x B(16x8 bf16, col-major) + 0, fp32 accum
__device__ __forceinline__ void mma16816(
    float& d0, float& d1, float& d2, float& d3,
    unsigned a0, unsigned a1, unsigned a2, unsigned a3,
    unsigned b0, unsigned b1)
{
    asm("mma.sync.aligned.m16n8k16.row.col.f32.bf16.bf16.f32 "
        "{%0,%1,%2,%3}, {%4,%5,%6,%7}, {%8,%9}, {%10,%11,%12,%13};"
        : "=f"(d0), "=f"(d1), "=f"(d2), "=f"(d3)
        : "r"(a0), "r"(a1), "r"(a2), "r"(a3), "r"(b0), "r"(b1),
          "f"(0.0f), "f"(0.0f), "f"(0.0f), "f"(0.0f));
}

// K-vector layouts (16 bf16 = 8 u32 words per point):
// P-vectors carry the exponent constants IN the MMA:
//   A: k = [H0,H1,H2, L0,L1,L2, H0,H1,H2, L0,L1,L2, Ch,Cl, 1, 1]
//   B: k = [H0,H1,H2, H0,H1,H2, L0,L1,L2, L0,L1,L2, 1, 1, Ch,Cl]
//   dot = (hi+lo)_i.(hi+lo)_j + ci + cj = -S*log2(e)  (<= 0)
// D-vectors: plain normals, slots 12-15 = 0.
// B stored PAIRED: [w0,w4, w1,w5, w2,w6, w3,w7] so lane tig reads its two
// fragment words (tig, tig+4) with one LDS.64 at word offset tig*2.

__device__ __forceinline__ void split_bf(float v, unsigned& h, unsigned& l) {
    h = bfb(v);
    l = bfb(v - bf2f(h));
}

__device__ __forceinline__ void write_A(unsigned* u, float v0, float v1, float v2,
                                        unsigned w6, unsigned w7) {
    unsigned h0, h1, h2, l0, l1, l2;
    split_bf(v0, h0, l0); split_bf(v1, h1, l1); split_bf(v2, h2, l2);
    const unsigned w0 = PK(h0, h1), w1 = PK(h2, l0), w2 = PK(l1, l2);
    u[0] = w0; u[1] = w1; u[2] = w2;
    u[3] = w0; u[4] = w1; u[5] = w2;
    u[6] = w6; u[7] = w7;
}
__device__ __forceinline__ void write_B_paired(unsigned* u, float v0, float v1, float v2,
                                               unsigned w6, unsigned w7) {
    unsigned h0, h1, h2, l0, l1, l2;
    split_bf(v0, h0, l0); split_bf(v1, h1, l1); split_bf(v2, h2, l2);
    u[0] = PK(h0, h1);  u[1] = PK(l2, l0);   // (w0, w4)
    u[2] = PK(h2, h0);  u[3] = PK(l1, l2);   // (w1, w5)
    u[4] = PK(h1, h2);  u[5] = w6;           // (w2, w6)
    u[6] = PK(l0, l1);  u[7] = w7;           // (w3, w7)
}

__global__ void __launch_bounds__(TPB, 4)
varifold_mma(const float* __restrict__ xyz1,
             const float* __restrict__ xyz2,
             const float* __restrict__ nor1,
             const float* __restrict__ nor2,
             float* __restrict__ out)
{
    __shared__ unsigned sIP[TILE * 8];   // i position K-vecs (A layout, with consts)
    __shared__ unsigned sID[TILE * 8];   // i normal K-vecs (A layout)
    __shared__ __align__(8) unsigned sJP[TILE * 8];   // j position K-vecs (B paired, consts)
    __shared__ __align__(8) unsigned sJD[TILE * 8];   // j normal K-vecs (B paired)
    __shared__ float warpsum[TPB / 32];

    const int tid  = threadIdx.x;
    const int wid  = tid >> 5;
    const int lane = tid & 31;
    const int g    = lane >> 2;          // groupID
    const int tig  = lane & 3;           // thread-in-group

    // ---- decode block -> (term, ti, tj, weight) ----
    int idx = blockIdx.x;                // 0..PAIRS-1
    const int b = blockIdx.y;
    int term, ti, tj;
    float w;
    if (idx < 2 * NSYM) {
        term = (idx < NSYM) ? 0 : 1;
        int k = (idx < NSYM) ? idx : idx - NSYM;
        ti = 0;
        while (k >= T - ti) { k -= T - ti; ti++; }
        tj = ti + k;
        w = (ti == tj) ? 1.0f : 2.0f;    // symmetric: off-diag counted twice
    } else {
        term = 2;
        const int q = idx - 2 * NSYM;
        ti = q >> 4;                     // T == 16
        tj = q & (T - 1);
        w = -2.0f;
    }

    const float* xa; const float* xb; const float* na; const float* nb;
    if (term == 0)      { xa = xyz1; xb = xyz1; na = nor1; nb = nor1; }
    else if (term == 1) { xa = xyz2; xb = xyz2; na = nor2; nb = nor2; }
    else                { xa = xyz1; xb = xyz2; na = nor1; nb = nor2; }
    const long boff = (long)b * NPTS * 3;
    xa += boff; xb += boff; na += boff; nb += boff;

    // ---- fill smem K-vectors ----
    {
        const int ip = ti * TILE + tid;
        const float px = xa[ip * 3 + 0] * COORD_SCALE2;
        const float py = xa[ip * 3 + 1] * COORD_SCALE2;
        const float pz = xa[ip * 3 + 2] * COORD_SCALE2;
        const float ci = -0.5f * (px * px + py * py + pz * pz);
        unsigned ch, cl;
        split_bf(ci, ch, cl);
        write_A(&sIP[tid * 8], px, py, pz, PK(ch, cl), PK(BF_ONE, BF_ONE));
        write_A(&sID[tid * 8], na[ip * 3 + 0], na[ip * 3 + 1], na[ip * 3 + 2], 0u, 0u);

        const int jp = tj * TILE + tid;
        const float qx = xb[jp * 3 + 0] * COORD_SCALE2;
        const float qy = xb[jp * 3 + 1] * COORD_SCALE2;
        const float qz = xb[jp * 3 + 2] * COORD_SCALE2;
        const float cj = -0.5f * (qx * qx + qy * qy + qz * qz);
        unsigned dh, dl;
        split_bf(cj, dh, dl);
        write_B_paired(&sJP[tid * 8], qx, qy, qz, PK(BF_ONE, BF_ONE), PK(dh, dl));
        write_B_paired(&sJD[tid * 8], nb[jp * 3 + 0], nb[jp * 3 + 1], nb[jp * 3 + 2], 0u, 0u);
    }
    __syncthreads();

    // ---- hoist A fragments for BOTH i-subtiles ----
    unsigned aP[ISUB][4], aD[ISUB][4];
    #pragma unroll
    for (int s = 0; s < ISUB; s++) {
        const int row = s * 128 + wid * 16 + g;
        aP[s][0] = sIP[row * 8 + tig];
        aP[s][1] = sIP[(row + 8) * 8 + tig];
        aP[s][2] = sIP[row * 8 + 4 + tig];
        aP[s][3] = sIP[(row + 8) * 8 + 4 + tig];
        aD[s][0] = sID[row * 8 + tig];
        aD[s][1] = sID[(row + 8) * 8 + tig];
        aD[s][2] = sID[row * 8 + 4 + tig];
        aD[s][3] = sID[(row + 8) * 8 + 4 + tig];
    }

    // ---- main loop ----
    ull acc01 = 0ull, acc23 = 0ull;      // f32x2 accumulators

    int jb = g * 8 + tig * 2;            // paired layout: lane's LDS.64 word offset
    #pragma unroll 4
    for (int js = 0; js < JSTEPS; js++) {
        const uint2 bp = *(const uint2*)&sJP[jb];   // (b0, b1) position
        const uint2 bd = *(const uint2*)&sJD[jb];   // (b0, b1) normal

        #pragma unroll
        for (int s = 0; s < ISUB; s++) {
            float p0, p1, p2, p3, d0, d1, d2, d3;
            mma16816(p0, p1, p2, p3, aP[s][0], aP[s][1], aP[s][2], aP[s][3], bp.x, bp.y);
            mma16816(d0, d1, d2, d3, aD[s][0], aD[s][1], aD[s][2], aD[s][3], bd.x, bd.y);

            // packed exponentials in f16 (10-bit mantissa): e = 2^P, P = -S*log2(e) <= 0
            const unsigned hA = pack_f16x2(p0, p1);
            const unsigned hB = pack_f16x2(p2, p3);
            const unsigned eA = ex2_f16x2(hA);
            const unsigned eB = ex2_f16x2(hB);
            float e0, e1, e2, e3;
            unpack_f16x2(eA, e0, e1);
            unpack_f16x2(eB, e2, e3);

            // acc += e * D^2   (f32x2 packed)
            const ull E01 = pack2(e0, e1);
            const ull E23 = pack2(e2, e3);
            const ull D01 = pack2(d0, d1);
            const ull D23 = pack2(d2, d3);
            const ull S01 = mul2(D01, D01);
            const ull S23 = mul2(D23, D23);
            acc01 = fma2(E01, S01, acc01);
            acc23 = fma2(E23, S23, acc23);
        }
        jb += 64;                        // next 8 j-vectors
    }

    // ---- block reduction (deterministic) ----
    float v;
    {
        float a0, a1, a2, a3;
        unpack2(acc01, a0, a1);
        unpack2(acc23, a2, a3);
        v = w * ((a0 + a1) + (a2 + a3));
    }
    #pragma unroll
    for (int o = 16; o > 0; o >>= 1)
        v += __shfl_xor_sync(0xffffffffu, v, o);
    if ((tid & 31) == 0) warpsum[tid >> 5] = v;
    __syncthreads();

    __shared__ bool is_last;
    if (tid == 0) {
        float s = 0.0f;
        #pragma unroll
        for (int k = 0; k < TPB / 32; k++) s += warpsum[k];
        const int blin = blockIdx.y * gridDim.x + blockIdx.x;
        g_partials[blin] = s;
        __threadfence();
        const unsigned int done = atomicAdd(&g_count, 1u);
        is_last = (done == (unsigned int)(NBLOCKS - 1));
    }
    __syncthreads();

    // ---- last block finalizes (fixed order => deterministic) ----
    if (is_last) {
        float r = 0.0f;
        for (int i = tid; i < NBLOCKS; i += TPB)
            r += __ldcg(&g_partials[i]);
        #pragma unroll
        for (int o = 16; o > 0; o >>= 1)
            r += __shfl_xor_sync(0xffffffffu, r, o);
        if ((tid & 31) == 0) warpsum[tid >> 5] = r;
        __syncthreads();
        if (tid == 0) {
            float s = 0.0f;
            #pragma unroll
            for (int k = 0; k < TPB / 32; k++) s += warpsum[k];
            out[0] = s;
            g_count = 0;   // reset for next graph replay
        }
    }
}

extern "C" void kernel_launch(void* const* d_in, const int* in_sizes, int n_in,
                              void* d_out, int out_size)
{
    const float* xyz1 = (const float*)d_in[0];
    const float* xyz2 = (const float*)d_in[1];
    const float* nor1 = (const float*)d_in[2];
    const float* nor2 = (const float*)d_in[3];

    dim3 grid(PAIRS, BATCH);
    varifold_mma<<<grid, TPB>>>(xyz1, xyz2, nor1, nor2, (float*)d_out);
}